// round 13
// baseline (speedup 1.0000x reference)
#include <cuda_runtime.h>
#include <math.h>

// Problem constants
#define BB  64
#define TT  512
#define II  256
#define OO  1024
#define MM  8
#define IMD 2048

// Persistent-kernel configuration
#define NB   128            // persistent blocks (co-resident: 128 <= SM count)
#define NTH  512
#define TK   8              // K-chunk depth
#define TILEN 256           // output-cols per tile
#define ARPAD 68            // padded A smem row (floats), swizzle-friendly
#define WROW  512           // duplicated W smem row (floats) = 2*TILEN
#define NSLOT 12            // split-K ways: rec 12, act 8

// packed fp32x2 FMA (Blackwell): d = a*b + d per 32-bit lane (exact fp32)
#define FMA2(d, a, b) asm("fma.rn.f32x2 %0, %1, %2, %0;" : "+l"(d) : "l"(a), "l"(b))

// ---------------------------------------------------------------------------
// Device state (allocation-free).  Column-major activations: [col][batch].
// ---------------------------------------------------------------------------
__device__ float g_xT[(size_t)TT * II * BB];   // x transposed: [t][i][b]
__device__ float g_WinT[(size_t)II * OO];      // W_in^T  [k][n]
__device__ float g_WhT [(size_t)OO * OO];      // W_h^T   [k][n]
__device__ float g_WirT[(size_t)II * IMD];     // W_ir^T  [k][n]
__device__ float g_WhrT[(size_t)IMD * IMD];    // W_hr^T  [k][n]
__device__ float g_xp[2][(size_t)IMD * BB];    // x_pred col-major, ping-pong
__device__ float g_hT[(size_t)OO * BB];        // hidden col-major
__device__ float g_lse[2][IMD];                // batch-axis logsumexp
__device__ float g_gate[BB * MM];
__device__ float g_part[NSLOT][(size_t)(IMD + OO) * BB]; // partials [col][b]
__device__ unsigned g_arrive;
__device__ volatile unsigned g_release;

// ---------------------------------------------------------------------------
__global__ void init_kernel(const float* __restrict__ x,
                            const float* __restrict__ W_in,
                            const float* __restrict__ W_h,
                            const float* __restrict__ W_ir,
                            const float* __restrict__ W_hr) {
    size_t i = (size_t)blockIdx.x * blockDim.x + threadIdx.x;
    size_t n = (size_t)gridDim.x * blockDim.x;
    for (size_t j = i; j < (size_t)TT * II * BB; j += n) {
        size_t b = j & 63, ti = j >> 6;
        size_t ii = ti % II, tt = ti / II;
        g_xT[j] = x[(b * TT + tt) * II + ii];
    }
    for (size_t j = i; j < (size_t)II * OO; j += n) {
        size_t nn = j % OO, k = j / OO;
        g_WinT[j] = W_in[nn * II + k];
    }
    for (size_t j = i; j < (size_t)OO * OO; j += n) {
        size_t nn = j % OO, k = j / OO;
        g_WhT[j] = W_h[nn * OO + k];
    }
    for (size_t j = i; j < (size_t)II * IMD; j += n) {
        size_t nn = j % IMD, k = j / IMD;
        g_WirT[j] = W_ir[nn * II + k];
    }
    for (size_t j = i; j < (size_t)IMD * IMD; j += n) {
        size_t nn = j % IMD, k = j / IMD;
        g_WhrT[j] = W_hr[nn * IMD + k];
    }
    for (size_t j = i; j < (size_t)IMD * BB; j += n) g_xp[0][j] = 0.f;
    for (size_t j = i; j < (size_t)OO * BB;  j += n) g_hT[j] = 0.f;
    for (size_t j = i; j < IMD; j += n) g_lse[0][j] = logf((float)BB);
    if (i == 0) { g_arrive = 0u; g_release = 0u; }
}

// Grid-wide barrier (all NB blocks resident by construction)
__device__ __forceinline__ void gbar(unsigned gen) {
    __syncthreads();
    if (threadIdx.x == 0) {
        __threadfence();
        unsigned v = atomicAdd(&g_arrive, 1u);
        if (v == gen * NB + (NB - 1u)) {
            g_release = gen + 1u;
        } else {
            while (g_release <= gen) { __nanosleep(64); }
        }
    }
    __syncthreads();
}

// ---------------------------------------------------------------------------
// Whole scan, one kernel. Per step: P1 GEMM(+gate) | bar | P2 reduce+act+LSE | bar
// ---------------------------------------------------------------------------
__global__ void __launch_bounds__(NTH) rnn_persistent(
    const float* __restrict__ x,
    const float* __restrict__ b_in, const float* __restrict__ b_ir,
    const float* __restrict__ periods, const float* __restrict__ shifts,
    float* __restrict__ ys, float* __restrict__ hfin, float* __restrict__ ps)
{
    __shared__ __align__(16) float AsB[2][TK * ARPAD];  // swizzled A [k][68]
    __shared__ __align__(16) float WsB[2][TK * WROW];   // splatted W [k][512]
    float* red = &AsB[0][0];                 // scratch alias (reductions)

    const int tid = threadIdx.x;
    const int bid = blockIdx.x;

    // Per-block static tile assignment (no runtime divisions in the hot loop)
    const bool recb = (bid < 96);
    const int tile  = recb ? (bid / 12) : ((bid - 96) / 8);
    const int slot  = recb ? (bid % 12) : ((bid - 96) % 8);
    const int koff  = slot * (recb ? 192 : 160);
    const int nch   = recb ? 24 : 20;                 // chunks of TK=8
    const int n0    = tile * TILEN;                   // col offset within W
    const int col0  = recb ? n0 : (IMD + n0);         // global partial col
    const float* W1 = recb ? g_WirT : g_WinT;         // k <  II source
    const float* W2 = recb ? g_WhrT : g_WhT;          // k >= II source
    const int ldw   = recb ? IMD : OO;

    // GEMM thread tile: 8 batches x 4 outputs
    const int g   = tid & 7;                  // batch group
    const int b0  = g * 8;                    // batches b0..b0+7
    const int boff = g * 8 + (g >> 2) * 4;    // swizzled smem float offset
    const int o0  = (tid >> 3) * 4;           // outputs o0..o0+3 (0..252)
    // Loader indices
    const int ak  = tid >> 4, ac = tid & 15;                // A: k, 16B-chunk
    const int adst = ak * 17 + ac + (ac >> 3);              // swizzled f4 idx
    const int wrow = tid >> 6;                              // W: k row (0..7)
    const int wcol = (tid & 63) * 4;                        // float offset

    unsigned gen = 0;
    for (int t = 0; t < TT; t++) {
        const int cur = t & 1, nxt = cur ^ 1;

        // ================= P1: one 64x256 tile, K-slice [koff, koff+nch*8) ==
        unsigned long long acc[4][4];
        #pragma unroll
        for (int j = 0; j < 4; j++)
            #pragma unroll
            for (int q = 0; q < 4; q++) acc[j][q] = 0ull;

        float4 av, wv;
        {   // preload chunk 0
            const int k0 = koff;
            const float* Ap; const float* Wp; bool cg;
            if (k0 < II) { Ap = g_xT + ((size_t)t * II + k0) * BB;
                           Wp = W1 + (size_t)k0 * ldw + n0; cg = false; }
            else { const int kk = k0 - II;
                   Ap = (recb ? g_xp[cur] : g_hT) + (size_t)kk * BB;
                   Wp = W2 + (size_t)kk * ldw + n0; cg = true; }
            if (tid < 128) {
                const float4* A4 = (const float4*)Ap;
                av = cg ? __ldcg(A4 + tid) : A4[tid];
            }
            wv = *(const float4*)(Wp + (size_t)wrow * ldw + wcol);
        }
        {   // store chunk 0 -> buffer 0 (W splatted into f32x2 lanes)
            if (tid < 128) ((float4*)AsB[0])[adst] = av;
            float* wd = &WsB[0][wrow * WROW + 2 * wcol];
            ((float4*)wd)[0] = make_float4(wv.x, wv.x, wv.y, wv.y);
            ((float4*)wd)[1] = make_float4(wv.z, wv.z, wv.w, wv.w);
        }

        int p = 0;
        for (int c = 0; c < nch; ++c) {
            __syncthreads();   // buf p stores visible; prior reads of p^1 done

            if (c + 1 < nch) {  // prefetch next chunk into regs
                const int k0 = koff + (c + 1) * TK;
                const float* Ap; const float* Wp; bool cg;
                if (k0 < II) { Ap = g_xT + ((size_t)t * II + k0) * BB;
                               Wp = W1 + (size_t)k0 * ldw + n0; cg = false; }
                else { const int kk = k0 - II;
                       Ap = (recb ? g_xp[cur] : g_hT) + (size_t)kk * BB;
                       Wp = W2 + (size_t)kk * ldw + n0; cg = true; }
                if (tid < 128) {
                    const float4* A4 = (const float4*)Ap;
                    av = cg ? __ldcg(A4 + tid) : A4[tid];
                }
                wv = *(const float4*)(Wp + (size_t)wrow * ldw + wcol);
            }

            // compute on buffer p: per k, 4 LDS.128 + 16 FFMA2 (32 MACs)
            {
                const float* Ar = AsB[p];
                const float* Wr = WsB[p];
                #pragma unroll
                for (int k = 0; k < TK; ++k) {
                    ulonglong2 a01 = *(const ulonglong2*)(Ar + k * ARPAD + boff);
                    ulonglong2 a23 = *(const ulonglong2*)(Ar + k * ARPAD + boff + 4);
                    ulonglong2 wA  = *(const ulonglong2*)(Wr + k * WROW + 2 * o0);
                    ulonglong2 wB  = *(const ulonglong2*)(Wr + k * WROW + 2 * o0 + 4);
                    FMA2(acc[0][0], a01.x, wA.x); FMA2(acc[0][1], a01.y, wA.x);
                    FMA2(acc[0][2], a23.x, wA.x); FMA2(acc[0][3], a23.y, wA.x);
                    FMA2(acc[1][0], a01.x, wA.y); FMA2(acc[1][1], a01.y, wA.y);
                    FMA2(acc[1][2], a23.x, wA.y); FMA2(acc[1][3], a23.y, wA.y);
                    FMA2(acc[2][0], a01.x, wB.x); FMA2(acc[2][1], a01.y, wB.x);
                    FMA2(acc[2][2], a23.x, wB.x); FMA2(acc[2][3], a23.y, wB.x);
                    FMA2(acc[3][0], a01.x, wB.y); FMA2(acc[3][1], a01.y, wB.y);
                    FMA2(acc[3][2], a23.x, wB.y); FMA2(acc[3][3], a23.y, wB.y);
                }
            }

            if (c + 1 < nch) {  // store prefetched chunk -> buffer p^1
                const int q = p ^ 1;
                if (tid < 128) ((float4*)AsB[q])[adst] = av;
                float* wd = &WsB[q][wrow * WROW + 2 * wcol];
                ((float4*)wd)[0] = make_float4(wv.x, wv.x, wv.y, wv.y);
                ((float4*)wd)[1] = make_float4(wv.z, wv.z, wv.w, wv.w);
            }
            p ^= 1;
        }
        {   // flush partials (single tile per block)
            float* base = g_part[slot] + ((size_t)(col0 + o0)) * BB + b0;
            #pragma unroll
            for (int j = 0; j < 4; j++) {
                ulonglong2 v0; v0.x = acc[j][0]; v0.y = acc[j][1];
                ulonglong2 v1; v1.x = acc[j][2]; v1.y = acc[j][3];
                *(ulonglong2*)(base + (size_t)j * BB)     = v0;
                *(ulonglong2*)(base + (size_t)j * BB + 4) = v1;
            }
        }

        // ---- P1b: surprisal dot -> gate (previous step's xp & lse) ----
        // 512 jobs (b,m); each block does 4, two at a time (tid>>8 picks job).
        #pragma unroll
        for (int it = 0; it < 2; ++it) {
            const int d = bid + (it * 2 + (tid >> 8)) * NB;  // 0..511
            const int b = d >> 3, m = d & 7;
            const int i = tid & 255;
            float xv  = x[((size_t)b * TT + t) * II + i];
            float xpv = __ldcg(&g_xp[cur][(size_t)(m * II + i) * BB + b]);
            float lsv = __ldcg(&g_lse[cur][m * II + i]);
            float part = (xpv - lsv) * xv;
            #pragma unroll
            for (int off = 16; off; off >>= 1)
                part += __shfl_xor_sync(0xffffffffu, part, off);
            __syncthreads();
            if ((tid & 31) == 0) red[tid >> 5] = part;
            __syncthreads();
            if ((tid & 255) == 0) {
                const int g8 = (tid >> 8) * 8;
                float tot = 0.f;
                #pragma unroll
                for (int w = 0; w < 8; w++) tot += red[g8 + w];
                float mp = tot * (1.0f / II) * periods[m];
                float gate = (sinf((float)t * mp + shifts[m]) + 1.f) * 0.5f;
                g_gate[d] = gate;
                ps[((size_t)b * TT + t) * MM + m] = mp;
            }
        }

        gbar(gen++);

        // ============ P2: reduce + activate + blend + fused LSE ============
        {
            float* redm = &AsB[0][0];
            float* reds = &AsB[0][16];
            const int c0p = bid * 24;
            const int bb  = tid & 63;
            const int clq = tid >> 6;     // 0..7
            const int w   = tid >> 5;     // 0..15
            #pragma unroll
            for (int pass = 0; pass < 3; ++pass) {
                const int col = c0p + pass * 8 + clq;
                const bool isrec = col < IMD;
                const int nslots = isrec ? 12 : 8;
                float s = 0.f;
                for (int sl = 0; sl < nslots; ++sl)
                    s += __ldcg(&g_part[sl][(size_t)col * BB + bb]);
                float v = 0.f;
                if (isrec) {
                    v = tanhf(s + b_ir[col]);
                    g_xp[nxt][(size_t)col * BB + bb] = v;
                } else {
                    const int o = col - IMD;
                    float a  = tanhf(s + b_in[o]);
                    float gt = __ldcg(&g_gate[bb * MM + (o >> 7)]);
                    float hv = g_hT[(size_t)o * BB + bb];
                    float y  = (1.f - gt) * a + gt * hv;
                    g_hT[(size_t)o * BB + bb] = y;
                    ys[((size_t)bb * TT + t) * OO + o] = y;
                }
                // column LSE over 64 batches (2 warps); act cols -> junk, unused
                float mx = v;
                #pragma unroll
                for (int off = 16; off; off >>= 1)
                    mx = fmaxf(mx, __shfl_xor_sync(0xffffffffu, mx, off));
                float se = isrec ? expf(v - mx) : 0.f;
                #pragma unroll
                for (int off = 16; off; off >>= 1)
                    se += __shfl_xor_sync(0xffffffffu, se, off);
                __syncthreads();
                if ((tid & 31) == 0) { redm[w] = mx; reds[w] = se; }
                __syncthreads();
                if (isrec && (tid & 63) == 0) {
                    float m0 = redm[w], m1 = redm[w + 1];
                    float M = fmaxf(m0, m1);
                    float S = reds[w] * expf(m0 - M) + reds[w + 1] * expf(m1 - M);
                    g_lse[nxt][col] = M + logf(S);
                }
            }
        }

        gbar(gen++);
    }

    // h_final: col-major -> [B][O]  (NB*NTH == BB*OO exactly)
    {
        int idx = bid * NTH + tid;
        int o = idx >> 6, b = idx & 63;
        hfin[(size_t)b * OO + o] = __ldcg(&g_hT[idx]);
    }
}

// ---------------------------------------------------------------------------
// 2 graph nodes. Inputs: x, W_in, b_in, W_h, W_ir, b_ir, W_hr, periods, shifts
// Output: concat(ys [B,T,O], h_final [B,O], ps [B,T,M]) fp32
// ---------------------------------------------------------------------------
extern "C" void kernel_launch(void* const* d_in, const int* in_sizes, int n_in,
                              void* d_out, int out_size) {
    const float* x       = (const float*)d_in[0];
    const float* W_in    = (const float*)d_in[1];
    const float* b_in    = (const float*)d_in[2];
    const float* W_h     = (const float*)d_in[3];
    const float* W_ir    = (const float*)d_in[4];
    const float* b_ir    = (const float*)d_in[5];
    const float* W_hr    = (const float*)d_in[6];
    const float* periods = (const float*)d_in[7];
    const float* shifts  = (const float*)d_in[8];

    float* out  = (float*)d_out;
    float* ys   = out;                                  // [B,T,O]
    float* hfin = out + (size_t)BB * TT * OO;           // [B,O]
    float* ps   = hfin + (size_t)BB * OO;               // [B,T,M]

    init_kernel<<<1024, 256>>>(x, W_in, W_h, W_ir, W_hr);
    rnn_persistent<<<NB, NTH>>>(x, b_in, b_ir, periods, shifts, ys, hfin, ps);
}